// round 2
// baseline (speedup 1.0000x reference)
#include <cuda_runtime.h>

// SpikeLoss: loss = 0.5 * sum( (outputs - psp(target))^2 ), tau = 5
// [B=32,C=256,H=4,W=4,T=100] -> 131072 rows x 100 steps.
// Smem-staged coalesced loads + per-thread register scan + fused deterministic
// single-pass reduction (last-block-done ticket).

#define T_STEPS   100
#define CHUNK     20           // time steps per smem tile
#define NCHUNK    5
#define VPC       (CHUNK / 4)  // float4 per row per chunk = 5
#define PAD       21           // smem row stride (coprime with 32 -> no LDS conflicts)
#define BLOCK     256          // threads per block == rows per block
#define MAX_BLOCKS 4096

__device__ float        g_partials[MAX_BLOCKS];
__device__ unsigned int g_count = 0;

__global__ void __launch_bounds__(BLOCK)
spike_loss_fused(const float* __restrict__ outputs,
                 const float* __restrict__ target,
                 float* __restrict__ out,
                 int rows)
{
    __shared__ float s_o[BLOCK * PAD];   // 21504 B
    __shared__ float s_x[BLOCK * PAD];   // 21504 B
    __shared__ float warp_sums[BLOCK / 32];
    __shared__ int   is_last;

    const int tid  = threadIdx.x;
    const int row0 = blockIdx.x * BLOCK;
    const int my_row = row0 + tid;

    const float decay   = 0.8f;   // 1 - 1/tau
    const float inv_tau = 0.2f;   // 1/tau
    float syn = 0.0f;
    float acc = 0.0f;

    const float4* __restrict__ o4 = reinterpret_cast<const float4*>(outputs);
    const float4* __restrict__ x4 = reinterpret_cast<const float4*>(target);
    const int row_v = T_STEPS / 4;   // 25 float4 per row

    for (int c = 0; c < NCHUNK; ++c) {
        // ---- coalesced stage: 256 rows x 20 steps (5 float4 per row) ----
        #pragma unroll
        for (int i = 0; i < VPC; ++i) {
            int idx = tid + i * BLOCK;        // 0..1279
            int r   = idx / VPC;              // row within block
            int v   = idx - r * VPC;          // float4 within chunk
            int gr  = row0 + r;
            if (gr < rows) {
                int gv = gr * row_v + c * VPC + v;
                float4 xo = __ldg(&x4[gv]);
                float4 oo = __ldg(&o4[gv]);
                int sb = r * PAD + v * 4;
                s_x[sb + 0] = xo.x; s_x[sb + 1] = xo.y;
                s_x[sb + 2] = xo.z; s_x[sb + 3] = xo.w;
                s_o[sb + 0] = oo.x; s_o[sb + 1] = oo.y;
                s_o[sb + 2] = oo.z; s_o[sb + 3] = oo.w;
            }
        }
        __syncthreads();

        // ---- register scan over this chunk (1 thread = 1 row) ----
        if (my_row < rows) {
            const int sb = tid * PAD;
            #pragma unroll
            for (int t = 0; t < CHUNK; ++t) {
                float x = s_x[sb + t];
                float o = s_o[sb + t];
                syn = fmaf(syn, decay, x);
                float d = fmaf(-syn, inv_tau, o);
                acc = fmaf(d, d, acc);
            }
        }
        __syncthreads();
    }

    // ---- block reduction (fixed tree order -> deterministic) ----
    const int lane = tid & 31;
    const int wid  = tid >> 5;
    #pragma unroll
    for (int off = 16; off > 0; off >>= 1)
        acc += __shfl_down_sync(0xFFFFFFFFu, acc, off);
    if (lane == 0) warp_sums[wid] = acc;
    __syncthreads();

    if (tid == 0) {
        float b = 0.0f;
        #pragma unroll
        for (int w = 0; w < BLOCK / 32; ++w) b += warp_sums[w];
        g_partials[blockIdx.x] = b;
        __threadfence();
        unsigned int ticket = atomicAdd(&g_count, 1u);
        is_last = (ticket == gridDim.x - 1) ? 1 : 0;
    }
    __syncthreads();

    // ---- last block finalizes: fixed-order sum of partials ----
    if (is_last) {
        const int nblocks = gridDim.x;
        float v = 0.0f;
        for (int i = tid; i < nblocks; i += BLOCK)
            v += g_partials[i];

        #pragma unroll
        for (int off = 16; off > 0; off >>= 1)
            v += __shfl_down_sync(0xFFFFFFFFu, v, off);
        if (lane == 0) warp_sums[wid] = v;
        __syncthreads();

        if (tid == 0) {
            float s = 0.0f;
            #pragma unroll
            for (int w = 0; w < BLOCK / 32; ++w) s += warp_sums[w];
            *out = 0.5f * s;
            g_count = 0;   // reset for next graph replay
        }
    }
}

extern "C" void kernel_launch(void* const* d_in, const int* in_sizes, int n_in,
                              void* d_out, int out_size)
{
    const float* outputs = (const float*)d_in[0];
    const float* target  = (const float*)d_in[1];
    float* out = (float*)d_out;

    const int n    = in_sizes[0];
    const int rows = n / T_STEPS;
    const int blocks = (rows + BLOCK - 1) / BLOCK;   // 512 for given shape

    spike_loss_fused<<<blocks, BLOCK>>>(outputs, target, out, rows);
}

// round 3
// speedup vs baseline: 1.0888x; 1.0888x over previous
#include <cuda_runtime.h>

// SpikeLoss: loss = 0.5 * sum( (outputs - psp(target))^2 ), tau = 5
// [32,256,4,4,100] -> 131072 rows x 100 steps.
// One WARP per row: lanes 0..24 hold 4 timesteps each (float4, fully
// coalesced 400B/warp/array). Linear recurrence solved with an affine
// warp scan: segment transform syn -> a*syn + b, a = decay^4.
// Fused deterministic reduction via last-block ticket.

#define T_STEPS   100
#define ROW_V     (T_STEPS / 4)   // 25 float4 per row
#define BLOCK     512
#define WPB       (BLOCK / 32)    // 16 rows per block
#define MAX_BLOCKS 16384

__device__ float        g_partials[MAX_BLOCKS];
__device__ unsigned int g_count = 0;

__global__ void __launch_bounds__(BLOCK)
spike_loss_warpscan(const float* __restrict__ outputs,
                    const float* __restrict__ target,
                    float* __restrict__ out,
                    int rows)
{
    const int tid  = threadIdx.x;
    const int lane = tid & 31;
    const int wid  = tid >> 5;
    const int row  = blockIdx.x * WPB + wid;

    const float decay   = 0.8f;
    const float inv_tau = 0.2f;
    const float decay4  = 0.4096f;   // 0.8^4

    float acc = 0.0f;

    if (row < rows) {
        const float4* __restrict__ x4 =
            reinterpret_cast<const float4*>(target)  + (size_t)row * ROW_V;
        const float4* __restrict__ o4 =
            reinterpret_cast<const float4*>(outputs) + (size_t)row * ROW_V;

        float4 x = make_float4(0.f, 0.f, 0.f, 0.f);
        float4 o = make_float4(0.f, 0.f, 0.f, 0.f);
        if (lane < ROW_V) {
            x = __ldg(&x4[lane]);
            o = __ldg(&o4[lane]);
        }

        // Local 4-step scan from zero state: b = syn after this segment.
        float s = x.x;
        s = fmaf(decay, s, x.y);
        s = fmaf(decay, s, x.z);
        s = fmaf(decay, s, x.w);
        float a = decay4;
        float b = s;

        // Inclusive affine warp scan: (a,b) := (a,b) ∘ (a_prev,b_prev)
        //   composed: syn -> a*(a_prev*syn + b_prev) + b
        #pragma unroll
        for (int off = 1; off < 32; off <<= 1) {
            float ap = __shfl_up_sync(0xFFFFFFFFu, a, off);
            float bp = __shfl_up_sync(0xFFFFFFFFu, b, off);
            if (lane >= off) {
                b = fmaf(a, bp, b);
                a *= ap;
            }
        }

        // Exclusive carry-in for this segment.
        float syn = __shfl_up_sync(0xFFFFFFFFu, b, 1);
        if (lane == 0) syn = 0.0f;

        if (lane < ROW_V) {
            float d;
            syn = fmaf(syn, decay, x.x); d = fmaf(-syn, inv_tau, o.x); acc = d * d;
            syn = fmaf(syn, decay, x.y); d = fmaf(-syn, inv_tau, o.y); acc = fmaf(d, d, acc);
            syn = fmaf(syn, decay, x.z); d = fmaf(-syn, inv_tau, o.z); acc = fmaf(d, d, acc);
            syn = fmaf(syn, decay, x.w); d = fmaf(-syn, inv_tau, o.w); acc = fmaf(d, d, acc);
        }
    }

    // ---- deterministic block reduction ----
    __shared__ float warp_sums[WPB];
    __shared__ int   is_last;

    #pragma unroll
    for (int off = 16; off > 0; off >>= 1)
        acc += __shfl_down_sync(0xFFFFFFFFu, acc, off);
    if (lane == 0) warp_sums[wid] = acc;
    __syncthreads();

    if (tid == 0) {
        float bsum = 0.0f;
        #pragma unroll
        for (int w = 0; w < WPB; ++w) bsum += warp_sums[w];
        g_partials[blockIdx.x] = bsum;
        __threadfence();
        unsigned int ticket = atomicAdd(&g_count, 1u);
        is_last = (ticket == gridDim.x - 1) ? 1 : 0;
    }
    __syncthreads();

    // ---- last block: fixed-order finalize ----
    if (is_last) {
        const int nblocks = gridDim.x;
        float v = 0.0f;
        for (int i = tid; i < nblocks; i += BLOCK)
            v += g_partials[i];

        #pragma unroll
        for (int off = 16; off > 0; off >>= 1)
            v += __shfl_down_sync(0xFFFFFFFFu, v, off);
        if (lane == 0) warp_sums[wid] = v;
        __syncthreads();

        if (tid == 0) {
            float stot = 0.0f;
            #pragma unroll
            for (int w = 0; w < WPB; ++w) stot += warp_sums[w];
            *out = 0.5f * stot;
            g_count = 0;   // reset for graph replay
        }
    }
}

extern "C" void kernel_launch(void* const* d_in, const int* in_sizes, int n_in,
                              void* d_out, int out_size)
{
    const float* outputs = (const float*)d_in[0];
    const float* target  = (const float*)d_in[1];
    float* out = (float*)d_out;

    const int n    = in_sizes[0];
    const int rows = n / T_STEPS;                  // 131072
    const int blocks = (rows + WPB - 1) / WPB;     // 8192

    spike_loss_warpscan<<<blocks, BLOCK>>>(outputs, target, out, rows);
}

// round 5
// speedup vs baseline: 1.5332x; 1.4082x over previous
#include <cuda_runtime.h>

// SpikeLoss: loss = 0.5 * sum( (outputs - psp(target))^2 ), tau = 5
// [32,256,4,4,100] -> 131072 rows x 100 steps, rows contiguous (stride 400B).
// One warp per 2 rows; lanes 0..24 hold one float4 (4 timesteps) of each row
// (fully coalesced). Linear recurrence via Kogge-Stone scan with COMPILE-TIME
// uniform multipliers (all segments length 4 -> a = 0.8^4 per lane, so round-r
// multiplier = (0.8^4)^(2^r) is a constant). Two independent rows interleaved
// for ILP. Fused deterministic reduction via last-block ticket.

#define T_STEPS   100
#define ROW_V     (T_STEPS / 4)   // 25 float4 per row
#define BLOCK     512
#define WPB       (BLOCK / 32)    // 16 warps -> 32 rows per block
#define MAX_BLOCKS 8192

__device__ float        g_partials[MAX_BLOCKS];
__device__ unsigned int g_count = 0;

__global__ void __launch_bounds__(BLOCK)
spike_loss_warpscan2(const float* __restrict__ outputs,
                     const float* __restrict__ target,
                     float* __restrict__ out,
                     int rows)
{
    const int tid  = threadIdx.x;
    const int lane = tid & 31;
    const int wid  = tid >> 5;
    const int rowA = (blockIdx.x * WPB + wid) * 2;
    const int rowB = rowA + 1;

    const float D  = 0.8f;    // decay = 1 - 1/tau
    const float IT = 0.2f;    // 1/tau

    const bool lv = (lane < ROW_V);
    const bool vA = lv && (rowA < rows);
    const bool vB = lv && (rowB < rows);

    float4 xa = make_float4(0.f,0.f,0.f,0.f), oa = xa;
    float4 xb = xa, ob = xa;

    {
        const float4* __restrict__ x4 = reinterpret_cast<const float4*>(target);
        const float4* __restrict__ o4 = reinterpret_cast<const float4*>(outputs);
        if (vA) { xa = __ldg(&x4[(size_t)rowA * ROW_V + lane]);
                  oa = __ldg(&o4[(size_t)rowA * ROW_V + lane]); }
        if (vB) { xb = __ldg(&x4[(size_t)rowB * ROW_V + lane]);
                  ob = __ldg(&o4[(size_t)rowB * ROW_V + lane]); }
    }

    // Local 4-step scan (zero init): b = syn after this lane's segment.
    float bA = fmaf(D, fmaf(D, fmaf(D, xa.x, xa.y), xa.z), xa.w);
    float bB = fmaf(D, fmaf(D, fmaf(D, xb.x, xb.y), xb.z), xb.w);

    // Kogge-Stone with compile-time uniform multipliers:
    // round r (off = 1<<r): b_i += (0.8^4)^(off) * b_{i-off}
    const float C[5] = { 0.4096f,               // 0.8^4
                         0.16777216f,           // ^2
                         2.8147497671e-2f,      // ^4
                         7.9228162514e-4f,      // ^8
                         6.2771017354e-7f };    // ^16
    #pragma unroll
    for (int r = 0; r < 5; ++r) {
        const int off = 1 << r;
        float pA = __shfl_up_sync(0xFFFFFFFFu, bA, off);
        float pB = __shfl_up_sync(0xFFFFFFFFu, bB, off);
        if (lane >= off) {
            bA = fmaf(C[r], pA, bA);
            bB = fmaf(C[r], pB, bB);
        }
    }

    // Exclusive carry-in.
    float sA = __shfl_up_sync(0xFFFFFFFFu, bA, 1);
    float sB = __shfl_up_sync(0xFFFFFFFFu, bB, 1);
    if (lane == 0) { sA = 0.0f; sB = 0.0f; }

    float acc = 0.0f;
    if (vA) {
        float d;
        sA = fmaf(sA, D, xa.x); d = fmaf(-sA, IT, oa.x); acc = fmaf(d, d, acc);
        sA = fmaf(sA, D, xa.y); d = fmaf(-sA, IT, oa.y); acc = fmaf(d, d, acc);
        sA = fmaf(sA, D, xa.z); d = fmaf(-sA, IT, oa.z); acc = fmaf(d, d, acc);
        sA = fmaf(sA, D, xa.w); d = fmaf(-sA, IT, oa.w); acc = fmaf(d, d, acc);
    }
    if (vB) {
        float d;
        sB = fmaf(sB, D, xb.x); d = fmaf(-sB, IT, ob.x); acc = fmaf(d, d, acc);
        sB = fmaf(sB, D, xb.y); d = fmaf(-sB, IT, ob.y); acc = fmaf(d, d, acc);
        sB = fmaf(sB, D, xb.z); d = fmaf(-sB, IT, ob.z); acc = fmaf(d, d, acc);
        sB = fmaf(sB, D, xb.w); d = fmaf(-sB, IT, ob.w); acc = fmaf(d, d, acc);
    }

    // ---- deterministic block reduction ----
    __shared__ float warp_sums[WPB];
    __shared__ int   is_last;

    #pragma unroll
    for (int off = 16; off > 0; off >>= 1)
        acc += __shfl_down_sync(0xFFFFFFFFu, acc, off);
    if (lane == 0) warp_sums[wid] = acc;
    __syncthreads();

    if (tid == 0) {
        float bsum = 0.0f;
        #pragma unroll
        for (int w = 0; w < WPB; ++w) bsum += warp_sums[w];
        g_partials[blockIdx.x] = bsum;
        __threadfence();
        unsigned int ticket = atomicAdd(&g_count, 1u);
        is_last = (ticket == gridDim.x - 1) ? 1 : 0;
    }
    __syncthreads();

    // ---- last block: fixed-order finalize ----
    if (is_last) {
        const int nblocks = gridDim.x;
        float v = 0.0f;
        for (int i = tid; i < nblocks; i += BLOCK)
            v += g_partials[i];

        #pragma unroll
        for (int off = 16; off > 0; off >>= 1)
            v += __shfl_down_sync(0xFFFFFFFFu, v, off);
        if (lane == 0) warp_sums[wid] = v;
        __syncthreads();

        if (tid == 0) {
            float stot = 0.0f;
            #pragma unroll
            for (int w = 0; w < WPB; ++w) stot += warp_sums[w];
            *out = 0.5f * stot;
            g_count = 0;   // reset for graph replay
        }
    }
}

extern "C" void kernel_launch(void* const* d_in, const int* in_sizes, int n_in,
                              void* d_out, int out_size)
{
    const float* outputs = (const float*)d_in[0];
    const float* target  = (const float*)d_in[1];
    float* out = (float*)d_out;

    const int n    = in_sizes[0];
    const int rows = n / T_STEPS;                       // 131072
    const int blocks = (rows + 2 * WPB - 1) / (2 * WPB); // 4096

    spike_loss_warpscan2<<<blocks, BLOCK>>>(outputs, target, out, rows);
}

// round 6
// speedup vs baseline: 2.2425x; 1.4627x over previous
#include <cuda_runtime.h>

// SpikeLoss: loss = 0.5 * sum( (outputs - psp(target))^2 ), tau = 5
// [32,256,4,4,100] -> 131072 rows x 100 steps, rows contiguous (400B each).
// Persistent grid-stride kernel: one warp processes 2 rows per iteration
// (lanes 0..24 hold one float4 = 4 timesteps each; fully coalesced loads).
// Linear recurrence via Kogge-Stone scan with compile-time uniform
// multipliers ((0.8^4)^(2^r)). No barriers inside the loop; one block
// reduction + deterministic last-block finalize per block (592 total).

#define T_STEPS   100
#define ROW_V     (T_STEPS / 4)   // 25 float4 per row
#define BLOCK     512
#define WPB       (BLOCK / 32)    // 16 warps -> 32 rows per iteration
#define GRID      592             // ~1 full wave on 148 SMs (4 blocks/SM)
#define MAX_BLOCKS 1024

__device__ float        g_partials[MAX_BLOCKS];
__device__ unsigned int g_count = 0;

__global__ void __launch_bounds__(BLOCK)
spike_loss_persist(const float* __restrict__ outputs,
                   const float* __restrict__ target,
                   float* __restrict__ out,
                   int rows)
{
    const int tid  = threadIdx.x;
    const int lane = tid & 31;
    const int wid  = tid >> 5;

    const float D  = 0.8f;    // decay = 1 - 1/tau
    const float IT = 0.2f;    // 1/tau

    const bool lv = (lane < ROW_V);
    const float4* __restrict__ x4 = reinterpret_cast<const float4*>(target);
    const float4* __restrict__ o4 = reinterpret_cast<const float4*>(outputs);

    // Kogge-Stone uniform multipliers: (0.8^4)^(2^r)
    const float C0 = 0.4096f;
    const float C1 = 0.16777216f;
    const float C2 = 2.8147497671e-2f;
    const float C3 = 7.9228162514e-4f;
    const float C4 = 6.2771017354e-7f;

    float acc = 0.0f;

    const int npairs = rows >> 1;                 // 65536 row-pairs
    // pair index for this warp, grid-strided
    for (int pair = blockIdx.x * WPB + wid; pair < npairs;
         pair += GRID * WPB) {

        const int rowA = pair * 2;
        const int rowB = rowA + 1;

        float4 xa = make_float4(0.f,0.f,0.f,0.f), oa = xa;
        float4 xb = xa, ob = xa;
        if (lv) {
            xa = __ldg(&x4[(size_t)rowA * ROW_V + lane]);
            xb = __ldg(&x4[(size_t)rowB * ROW_V + lane]);
            oa = __ldg(&o4[(size_t)rowA * ROW_V + lane]);
            ob = __ldg(&o4[(size_t)rowB * ROW_V + lane]);
        }

        // Local 4-step scan (zero init): b = syn after this lane's segment.
        float bA = fmaf(D, fmaf(D, fmaf(D, xa.x, xa.y), xa.z), xa.w);
        float bB = fmaf(D, fmaf(D, fmaf(D, xb.x, xb.y), xb.z), xb.w);

        // Kogge-Stone, two independent chains interleaved.
        float pA, pB;
        pA = __shfl_up_sync(0xFFFFFFFFu, bA, 1);
        pB = __shfl_up_sync(0xFFFFFFFFu, bB, 1);
        if (lane >= 1)  { bA = fmaf(C0, pA, bA); bB = fmaf(C0, pB, bB); }
        pA = __shfl_up_sync(0xFFFFFFFFu, bA, 2);
        pB = __shfl_up_sync(0xFFFFFFFFu, bB, 2);
        if (lane >= 2)  { bA = fmaf(C1, pA, bA); bB = fmaf(C1, pB, bB); }
        pA = __shfl_up_sync(0xFFFFFFFFu, bA, 4);
        pB = __shfl_up_sync(0xFFFFFFFFu, bB, 4);
        if (lane >= 4)  { bA = fmaf(C2, pA, bA); bB = fmaf(C2, pB, bB); }
        pA = __shfl_up_sync(0xFFFFFFFFu, bA, 8);
        pB = __shfl_up_sync(0xFFFFFFFFu, bB, 8);
        if (lane >= 8)  { bA = fmaf(C3, pA, bA); bB = fmaf(C3, pB, bB); }
        pA = __shfl_up_sync(0xFFFFFFFFu, bA, 16);
        pB = __shfl_up_sync(0xFFFFFFFFu, bB, 16);
        if (lane >= 16) { bA = fmaf(C4, pA, bA); bB = fmaf(C4, pB, bB); }

        // Exclusive carry-in.
        float sA = __shfl_up_sync(0xFFFFFFFFu, bA, 1);
        float sB = __shfl_up_sync(0xFFFFFFFFu, bB, 1);
        if (lane == 0) { sA = 0.0f; sB = 0.0f; }

        if (lv) {
            float d;
            sA = fmaf(sA, D, xa.x); d = fmaf(-sA, IT, oa.x); acc = fmaf(d, d, acc);
            sA = fmaf(sA, D, xa.y); d = fmaf(-sA, IT, oa.y); acc = fmaf(d, d, acc);
            sA = fmaf(sA, D, xa.z); d = fmaf(-sA, IT, oa.z); acc = fmaf(d, d, acc);
            sA = fmaf(sA, D, xa.w); d = fmaf(-sA, IT, oa.w); acc = fmaf(d, d, acc);
            sB = fmaf(sB, D, xb.x); d = fmaf(-sB, IT, ob.x); acc = fmaf(d, d, acc);
            sB = fmaf(sB, D, xb.y); d = fmaf(-sB, IT, ob.y); acc = fmaf(d, d, acc);
            sB = fmaf(sB, D, xb.z); d = fmaf(-sB, IT, ob.z); acc = fmaf(d, d, acc);
            sB = fmaf(sB, D, xb.w); d = fmaf(-sB, IT, ob.w); acc = fmaf(d, d, acc);
        }
    }

    // ---- once-per-block deterministic reduction ----
    __shared__ float warp_sums[WPB];
    __shared__ int   is_last;

    #pragma unroll
    for (int off = 16; off > 0; off >>= 1)
        acc += __shfl_down_sync(0xFFFFFFFFu, acc, off);
    if (lane == 0) warp_sums[wid] = acc;
    __syncthreads();

    if (tid == 0) {
        float bsum = 0.0f;
        #pragma unroll
        for (int w = 0; w < WPB; ++w) bsum += warp_sums[w];
        g_partials[blockIdx.x] = bsum;
        __threadfence();
        unsigned int ticket = atomicAdd(&g_count, 1u);
        is_last = (ticket == gridDim.x - 1) ? 1 : 0;
    }
    __syncthreads();

    // ---- last block: fixed-order finalize over GRID partials ----
    if (is_last) {
        const int nblocks = gridDim.x;
        float v = 0.0f;
        for (int i = tid; i < nblocks; i += BLOCK)
            v += g_partials[i];

        #pragma unroll
        for (int off = 16; off > 0; off >>= 1)
            v += __shfl_down_sync(0xFFFFFFFFu, v, off);
        if (lane == 0) warp_sums[wid] = v;
        __syncthreads();

        if (tid == 0) {
            float stot = 0.0f;
            #pragma unroll
            for (int w = 0; w < WPB; ++w) stot += warp_sums[w];
            *out = 0.5f * stot;
            g_count = 0;   // reset for graph replay
        }
    }
}

extern "C" void kernel_launch(void* const* d_in, const int* in_sizes, int n_in,
                              void* d_out, int out_size)
{
    const float* outputs = (const float*)d_in[0];
    const float* target  = (const float*)d_in[1];
    float* out = (float*)d_out;

    const int n    = in_sizes[0];
    const int rows = n / T_STEPS;   // 131072 (even -> pairs exact)

    spike_loss_persist<<<GRID, BLOCK>>>(outputs, target, out, rows);
}